// round 12
// baseline (speedup 1.0000x reference)
#include <cuda_runtime.h>
#include <math.h>

#define BB 8
#define HH 384
#define WW 384
#define CC 3
#define NPAR 6
#define DELTA 10
#define LAM 0.05f
#define TOLF 1e-3f
#define MAXIT 12

#define PIX (HH*WW)
#define VH (HH - 2*DELTA)   // 364

// k_iter: block 128x2, block covers 4 rows (R5-proven shape)
#define TBX 128
#define TBY 2
#define NTHR (TBX*TBY)      // 256
#define ROWS1 4
#define NBLK1 (VH/ROWS1)    // 91

#define FBX 128
#define FBY 2
#define ROWSF 4
#define NBLKF (HH/ROWSF)    // 96

// Output layout: pf[B*6] | err[B] | DI[B*H*W*C] | Iw[B*H*W*C]
#define OUT_P   0
#define OUT_ERR (BB*NPAR)
#define OUT_DI  (BB*NPAR + BB)
#define OUT_IW  (OUT_DI + BB*PIX*CC)

// -------- scratch --------
__device__ float g_I1p[BB*CC*PIX];
__device__ float g_I2p[BB*CC*PIX];
__device__ float g_p[BB*NPAR];
__device__ int   g_done[BB];
__device__ float g_part[BB*NBLK1*27];
__device__ int   g_cnt[BB];
__device__ float g_fpart[BB*NBLKF*2];
__device__ int   g_fcnt[BB];

// -------- helpers --------
__device__ __forceinline__ float cubw(float s) {
    s = fabsf(s);
    float s2 = s*s, s3 = s2*s;
    float w1 = 1.5f*s3 - 2.5f*s2 + 1.0f;
    float w2 = -0.5f*s3 + 2.5f*s2 - 4.0f*s + 2.0f;
    return (s <= 1.0f) ? w1 : ((s < 2.0f) ? w2 : 0.0f);
}

// clamped version (k_final: samples outside the masked region too)
__device__ __forceinline__ void bicubic3(const float* __restrict__ I2b,
                                         float xg, float yg, float out[3]) {
    float x0 = floorf(xg), y0 = floorf(yg);
    float tx = xg - x0, ty = yg - y0;
    int xi = (int)x0, yi = (int)y0;
    float wx[4], wy[4];
    int xx[4], yy[4];
#pragma unroll
    for (int k = 0; k < 4; k++) {
        wx[k] = cubw(tx - (float)(k - 1));
        wy[k] = cubw(ty - (float)(k - 1));
        int xc = xi + k - 1; xc = xc < 0 ? 0 : (xc > WW-1 ? WW-1 : xc);
        int yc = yi + k - 1; yc = yc < 0 ? 0 : (yc > HH-1 ? HH-1 : yc);
        xx[k] = xc; yy[k] = yc;
    }
#pragma unroll
    for (int c = 0; c < CC; c++) {
        const float* pc = I2b + c*PIX;
        float acc = 0.0f;
#pragma unroll
        for (int j = 0; j < 4; j++) {
            const float* pr = pc + yy[j]*WW;
            float r = wx[0]*__ldg(pr+xx[0]) + wx[1]*__ldg(pr+xx[1])
                    + wx[2]*__ldg(pr+xx[2]) + wx[3]*__ldg(pr+xx[3]);
            acc = fmaf(wy[j], r, acc);
        }
        out[c] = acc;
    }
}

// unclamped version: caller guarantees 10 <= rint(xg),rint(yg) <= 374,
// so taps span [8,376] subset [0,383] -- clamps are dead code.
__device__ __forceinline__ void bicubic3_nc(const float* __restrict__ I2b,
                                            float xg, float yg, float out[3]) {
    float x0 = floorf(xg), y0 = floorf(yg);
    float tx = xg - x0, ty = yg - y0;
    int xi = (int)x0, yi = (int)y0;
    float wx[4], wy[4];
#pragma unroll
    for (int k = 0; k < 4; k++) {
        wx[k] = cubw(tx - (float)(k - 1));
        wy[k] = cubw(ty - (float)(k - 1));
    }
    const float* base = I2b + (yi-1)*WW + (xi-1);
#pragma unroll
    for (int c = 0; c < CC; c++) {
        const float* pc = base + c*PIX;
        float acc = 0.0f;
#pragma unroll
        for (int j = 0; j < 4; j++) {
            const float* pr = pc + j*WW;
            float r = wx[0]*__ldg(pr+0) + wx[1]*__ldg(pr+1)
                    + wx[2]*__ldg(pr+2) + wx[3]*__ldg(pr+3);
            acc = fmaf(wy[j], r, acc);
        }
        out[c] = acc;
    }
}

// -------- init: planarize images, load p, reset state --------
__global__ void k_init(const float* __restrict__ I1,
                       const float* __restrict__ I2,
                       const float* __restrict__ pin) {
    int gid = blockIdx.x*blockDim.x + threadIdx.x;
    if (gid < BB*NPAR) g_p[gid] = pin[gid];
    if (gid < BB) { g_done[gid] = 0; g_cnt[gid] = 0; g_fcnt[gid] = 0; }
    if (gid < BB*PIX) {
        int b = gid / PIX;
        int r = gid - b*PIX;
#pragma unroll
        for (int c = 0; c < CC; c++) {
            int po = (b*CC + c)*PIX + r;
            g_I1p[po] = I1[gid*3 + c];
            g_I2p[po] = I2[gid*3 + c];
        }
    }
}

// -------- iteration: R5-style 27-accumulator reduction + fused solve --------
__global__ void __launch_bounds__(NTHR) k_iter() {
    int b = blockIdx.y;
    __shared__ float sred[NTHR/32][27];
    __shared__ int s_last;
    if (g_done[b]) return;
    const float* pb = &g_p[b*NPAR];
    float p0 = pb[0], p1 = pb[1], p2 = pb[2], p3 = pb[3], p4 = pb[4], p5 = pb[5];
    const float* I1b = g_I1p + b*CC*PIX;
    const float* I2b = g_I2p + b*CC*PIX;

    float acc[27];
#pragma unroll
    for (int k = 0; k < 27; k++) acc[k] = 0.0f;

    int rbase = DELTA + blockIdx.x*ROWS1 + threadIdx.y;
    for (int hr = 0; hr < ROWS1; hr += TBY) {
        int h = rbase + hr;
        float Y = (float)h;
        for (int w = DELTA + threadIdx.x; w < WW - DELTA; w += TBX) {
            float X = (float)w;
            float xg = fmaf(1.0f + p2, X, fmaf(p3, Y, p0));
            float yg = fmaf(p4, X, fmaf(1.0f + p5, Y, p1));
            float gx = rintf(xg), gy = rintf(yg);
            if (!(gx >= (float)DELTA && gx <= (float)(WW-DELTA) &&
                  gy >= (float)DELTA && gy <= (float)(HH-DELTA))) continue;

            float Iw[3];
            bicubic3_nc(I2b, xg, yg, Iw);

#pragma unroll
            for (int c = 0; c < CC; c++) {
                const float* pc = I1b + c*PIX + h*WW + w;
                float Ic = __ldg(pc);
                float Ix = 0.5f*(__ldg(pc+1)  - __ldg(pc-1));
                float Iy = 0.5f*(__ldg(pc+WW) - __ldg(pc-WW));
                float DI = Iw[c] - Ic;
                float u  = DI * (1.0f/LAM);
                float wt = rsqrtf(fmaf(u, u, 1.0f));
                float wd = wt * DI;
                float d[6] = {Ix, Iy, Ix*X, Ix*Y, Iy*X, Iy*Y};
                float t[6];
#pragma unroll
                for (int m = 0; m < 6; m++) t[m] = wt * d[m];
                int id = 0;
#pragma unroll
                for (int m = 0; m < 6; m++)
#pragma unroll
                    for (int n = m; n < 6; n++) { acc[id] = fmaf(t[m], d[n], acc[id]); id++; }
#pragma unroll
                for (int m = 0; m < 6; m++) acc[21+m] = fmaf(d[m], wd, acc[21+m]);
            }
        }
    }

    int tid = threadIdx.y*TBX + threadIdx.x;
    int lane = tid & 31, wid = tid >> 5;
#pragma unroll
    for (int k = 0; k < 27; k++) {
        float v = acc[k];
#pragma unroll
        for (int o = 16; o > 0; o >>= 1) v += __shfl_xor_sync(0xffffffffu, v, o);
        if (lane == 0) sred[wid][k] = v;
    }
    __syncthreads();
    if (tid < 27) {
        float s = 0.0f;
#pragma unroll
        for (int wq = 0; wq < NTHR/32; wq++) s += sred[wq][tid];
        g_part[(b*NBLK1 + blockIdx.x)*27 + tid] = s;
    }

    // last-arriving block performs the solve
    __syncthreads();
    __threadfence();
    if (tid == 0) {
        int prev = atomicAdd(&g_cnt[b], 1);
        s_last = (prev == NBLK1 - 1);
        if (s_last) g_cnt[b] = 0;
    }
    __syncthreads();
    if (!s_last) return;

    // ---- parallel tail sum: 8 threads per entry, deterministic order ----
    __shared__ double st[27][8];
    __shared__ double sS[27];
    if (tid < 216) {
        int val = tid >> 3, j = tid & 7;
        double a = 0.0;
        for (int k = j; k < NBLK1; k += 8)
            a += (double)g_part[(b*NBLK1 + k)*27 + val];
        st[val][j] = a;
    }
    __syncthreads();
    if (tid < 27) {
        double a = 0.0;
#pragma unroll
        for (int j = 0; j < 8; j++) a += st[tid][j];
        sS[tid] = a;
    }
    __syncthreads();
    if (tid != 0) return;

    {
        __shared__ double sA[6][7];
        int id = 0;
        for (int m = 0; m < 6; m++)
            for (int n = m; n < 6; n++) { sA[m][n] = sS[id]; sA[n][m] = sS[id]; id++; }
        for (int m = 0; m < 6; m++) { sA[m][m] += 1e-6; sA[m][6] = sS[21+m]; }

        for (int k = 0; k < 6; k++) {
            int piv = k; double best = fabs(sA[k][k]);
            for (int i = k+1; i < 6; i++) { double vv = fabs(sA[i][k]); if (vv > best) { best = vv; piv = i; } }
            if (piv != k)
                for (int j = 0; j < 7; j++) { double tmp = sA[k][j]; sA[k][j] = sA[piv][j]; sA[piv][j] = tmp; }
            double inv = 1.0 / sA[k][k];
            for (int i = k+1; i < 6; i++) {
                double f = sA[i][k] * inv;
                for (int j = k; j < 7; j++) sA[i][j] -= f * sA[k][j];
            }
        }
        float dp[6];
        double n2 = 0.0;
        for (int i = 5; i >= 0; i--) {
            double vv = sA[i][6];
            for (int j = i+1; j < 6; j++) vv -= sA[i][j] * (double)dp[j];
            double di = vv / sA[i][i];
            dp[i] = (float)di;
            n2 += di*di;
        }

        float* pw = &g_p[b*NPAR];
        float q0 = pw[0], q1 = pw[1], q2 = pw[2], q3 = pw[3], q4 = pw[4], q5 = pw[5];
        float a00 = 1.0f+q2, a01 = q3, a02 = q0, a10 = q4, a11 = 1.0f+q5, a12 = q1;
        float b00 = 1.0f+dp[2], b01 = dp[3], b02 = dp[0], b10 = dp[4], b11 = 1.0f+dp[5], b12 = dp[1];
        float det = b00*b11 - b01*b10;
        float rdet = 1.0f/det;
        float c00 =  b11*rdet, c01 = -b01*rdet, c10 = -b10*rdet, c11 =  b00*rdet;
        float c02 = -(c00*b02 + c01*b12);
        float c12 = -(c10*b02 + c11*b12);
        pw[0] = a00*c02 + a01*c12 + a02;
        pw[1] = a10*c02 + a11*c12 + a12;
        pw[2] = a00*c00 + a01*c10 - 1.0f;
        pw[3] = a00*c01 + a01*c11;
        pw[4] = a10*c00 + a11*c10;
        pw[5] = a10*c01 + a11*c11 - 1.0f;
        if (sqrt(n2) < (double)TOLF) g_done[b] = 1;
    }
}

// -------- final pass: Iw, DI outputs + robust error (fused finalize) --------
__global__ void __launch_bounds__(FBX*FBY) k_final(float* __restrict__ out) {
    int b = blockIdx.y;
    __shared__ float sr[(FBX*FBY)/32][2];
    __shared__ int s_last;
    const float* pb = &g_p[b*NPAR];
    float p0 = pb[0], p1 = pb[1], p2 = pb[2], p3 = pb[3], p4 = pb[4], p5 = pb[5];
    const float* I1b = g_I1p + b*CC*PIX;
    const float* I2b = g_I2p + b*CC*PIX;
    float* outDI = out + OUT_DI + (size_t)b*PIX*CC;
    float* outIW = out + OUT_IW + (size_t)b*PIX*CC;

    float rsum = 0.0f, csum = 0.0f;
    int rbase = blockIdx.x*ROWSF + threadIdx.y;
    for (int hr = 0; hr < ROWSF; hr += FBY) {
        int h = rbase + hr;
        float Y = (float)h;
        bool rowok = (h >= DELTA && h < HH-DELTA);
        for (int w = threadIdx.x; w < WW; w += FBX) {
            float X = (float)w;
            float xg = fmaf(1.0f + p2, X, fmaf(p3, Y, p0));
            float yg = fmaf(p4, X, fmaf(1.0f + p5, Y, p1));
            float Iw[3];
            bicubic3(I2b, xg, yg, Iw);
            float gx = rintf(xg), gy = rintf(yg);
            bool wm = (gx >= (float)DELTA && gx <= (float)(WW-DELTA) &&
                       gy >= (float)DELTA && gy <= (float)(HH-DELTA));
            bool m = wm && rowok && (w >= DELTA && w < WW-DELTA);
            int po = h*WW + w;
#pragma unroll
            for (int c = 0; c < CC; c++) {
                float di = m ? (Iw[c] - __ldg(I1b + c*PIX + po)) : 0.0f;
                outDI[po*3 + c] = di;
                outIW[po*3 + c] = Iw[c];
                if (m) {
                    float u = di * (1.0f/LAM);
                    rsum += (2.0f*LAM*LAM) * (sqrtf(fmaf(u, u, 1.0f)) - 1.0f);
                    csum += 1.0f;
                }
            }
        }
    }

    int tid = threadIdx.y*FBX + threadIdx.x;
    int lane = tid & 31, wid = tid >> 5;
#pragma unroll
    for (int o = 16; o > 0; o >>= 1) {
        rsum += __shfl_xor_sync(0xffffffffu, rsum, o);
        csum += __shfl_xor_sync(0xffffffffu, csum, o);
    }
    if (lane == 0) { sr[wid][0] = rsum; sr[wid][1] = csum; }
    __syncthreads();
    if (tid < 2) {
        float s = 0.0f;
#pragma unroll
        for (int wq = 0; wq < (FBX*FBY)/32; wq++) s += sr[wq][tid];
        g_fpart[(b*NBLKF + blockIdx.x)*2 + tid] = s;
    }

    __syncthreads();
    __threadfence();
    if (tid == 0) {
        int prev = atomicAdd(&g_fcnt[b], 1);
        s_last = (prev == NBLKF - 1);
        if (s_last) g_fcnt[b] = 0;
    }
    __syncthreads();
    if (!s_last) return;

    if (tid == 0) {
        double r = 0.0, c = 0.0;
        for (int k = 0; k < NBLKF; k++) {
            r += (double)g_fpart[(b*NBLKF + k)*2 + 0];
            c += (double)g_fpart[(b*NBLKF + k)*2 + 1];
        }
        double cnt = c < 1.0 ? 1.0 : c;
        out[OUT_ERR + b] = (float)(r / cnt);
    }
    if (tid < NPAR) out[OUT_P + b*NPAR + tid] = g_p[b*NPAR + tid];
}

// -------- entry --------
extern "C" void kernel_launch(void* const* d_in, const int* in_sizes, int n_in,
                              void* d_out, int out_size) {
    const float* I1  = (const float*)d_in[0];
    const float* I2  = (const float*)d_in[1];
    const float* pin = (const float*)d_in[2];
    float* out = (float*)d_out;

    k_init<<<(BB*PIX + 255)/256, 256>>>(I1, I2, pin);
    for (int it = 0; it < MAXIT; it++)
        k_iter<<<dim3(NBLK1, BB), dim3(TBX, TBY)>>>();
    k_final<<<dim3(NBLKF, BB), dim3(FBX, FBY)>>>(out);
}

// round 13
// speedup vs baseline: 1.0587x; 1.0587x over previous
#include <cuda_runtime.h>
#include <math.h>

#define BB 8
#define HH 384
#define WW 384
#define CC 3
#define NPAR 6
#define DELTA 10
#define LAM 0.05f
#define TOLF 1e-3f
#define MAXIT 12

#define PIX (HH*WW)
#define VH (HH - 2*DELTA)   // 364

// k_iter: block 128x2, block covers 4 rows (R5-proven shape)
#define TBX 128
#define TBY 2
#define NTHR (TBX*TBY)      // 256
#define ROWS1 4
#define NBLK1 (VH/ROWS1)    // 91

#define FBX 128
#define FBY 2
#define ROWSF 4
#define NBLKF (HH/ROWSF)    // 96

// Output layout: pf[B*6] | err[B] | DI[B*H*W*C] | Iw[B*H*W*C]
#define OUT_P   0
#define OUT_ERR (BB*NPAR)
#define OUT_DI  (BB*NPAR + BB)
#define OUT_IW  (OUT_DI + BB*PIX*CC)

// -------- scratch --------
__device__ float g_I1p[BB*CC*PIX];
__device__ float g_I2p[BB*CC*PIX];
__device__ float g_p[BB*NPAR];
__device__ int   g_done[BB];
__device__ float g_part[BB*NBLK1*27];
__device__ int   g_cnt[BB];
__device__ float g_fpart[BB*NBLKF*2];
__device__ int   g_fcnt[BB];

// -------- helpers --------
__device__ __forceinline__ float cubw(float s) {
    s = fabsf(s);
    float s2 = s*s, s3 = s2*s;
    float w1 = 1.5f*s3 - 2.5f*s2 + 1.0f;
    float w2 = -0.5f*s3 + 2.5f*s2 - 4.0f*s + 2.0f;
    return (s <= 1.0f) ? w1 : ((s < 2.0f) ? w2 : 0.0f);
}

// clamped bicubic — exact R5 version (clamps ride the idle ALU pipe and
// this codegen is the proven-fast one)
__device__ __forceinline__ void bicubic3(const float* __restrict__ I2b,
                                         float xg, float yg, float out[3]) {
    float x0 = floorf(xg), y0 = floorf(yg);
    float tx = xg - x0, ty = yg - y0;
    int xi = (int)x0, yi = (int)y0;
    float wx[4], wy[4];
    int xx[4], yy[4];
#pragma unroll
    for (int k = 0; k < 4; k++) {
        wx[k] = cubw(tx - (float)(k - 1));
        wy[k] = cubw(ty - (float)(k - 1));
        int xc = xi + k - 1; xc = xc < 0 ? 0 : (xc > WW-1 ? WW-1 : xc);
        int yc = yi + k - 1; yc = yc < 0 ? 0 : (yc > HH-1 ? HH-1 : yc);
        xx[k] = xc; yy[k] = yc;
    }
#pragma unroll
    for (int c = 0; c < CC; c++) {
        const float* pc = I2b + c*PIX;
        float acc = 0.0f;
#pragma unroll
        for (int j = 0; j < 4; j++) {
            const float* pr = pc + yy[j]*WW;
            float r = wx[0]*__ldg(pr+xx[0]) + wx[1]*__ldg(pr+xx[1])
                    + wx[2]*__ldg(pr+xx[2]) + wx[3]*__ldg(pr+xx[3]);
            acc = fmaf(wy[j], r, acc);
        }
        out[c] = acc;
    }
}

// -------- init: planarize images, load p, reset state --------
__global__ void k_init(const float* __restrict__ I1,
                       const float* __restrict__ I2,
                       const float* __restrict__ pin) {
    int gid = blockIdx.x*blockDim.x + threadIdx.x;
    if (gid < BB*NPAR) g_p[gid] = pin[gid];
    if (gid < BB) { g_done[gid] = 0; g_cnt[gid] = 0; g_fcnt[gid] = 0; }
    if (gid < BB*PIX) {
        int b = gid / PIX;
        int r = gid - b*PIX;
#pragma unroll
        for (int c = 0; c < CC; c++) {
            int po = (b*CC + c)*PIX + r;
            g_I1p[po] = I1[gid*3 + c];
            g_I2p[po] = I2[gid*3 + c];
        }
    }
}

// -------- iteration: R5 27-accumulator body + fused parallel solve --------
// launch_bounds(256,3): reg cap 85 — room for the ~80-reg R5 allocation,
// prevents the 64-reg/4-CTA heuristic that spilled the accumulators in R12.
__global__ void __launch_bounds__(NTHR, 3) k_iter() {
    int b = blockIdx.y;
    __shared__ float sred[NTHR/32][27];
    __shared__ int s_last;
    if (g_done[b]) return;
    const float* pb = &g_p[b*NPAR];
    float p0 = pb[0], p1 = pb[1], p2 = pb[2], p3 = pb[3], p4 = pb[4], p5 = pb[5];
    const float* I1b = g_I1p + b*CC*PIX;
    const float* I2b = g_I2p + b*CC*PIX;

    float acc[27];
#pragma unroll
    for (int k = 0; k < 27; k++) acc[k] = 0.0f;

    int rbase = DELTA + blockIdx.x*ROWS1 + threadIdx.y;
    for (int hr = 0; hr < ROWS1; hr += TBY) {
        int h = rbase + hr;
        float Y = (float)h;
        for (int w = DELTA + threadIdx.x; w < WW - DELTA; w += TBX) {
            float X = (float)w;
            float xg = fmaf(1.0f + p2, X, fmaf(p3, Y, p0));
            float yg = fmaf(p4, X, fmaf(1.0f + p5, Y, p1));
            float gx = rintf(xg), gy = rintf(yg);
            if (!(gx >= (float)DELTA && gx <= (float)(WW-DELTA) &&
                  gy >= (float)DELTA && gy <= (float)(HH-DELTA))) continue;

            float Iw[3];
            bicubic3(I2b, xg, yg, Iw);

#pragma unroll
            for (int c = 0; c < CC; c++) {
                const float* pc = I1b + c*PIX + h*WW + w;
                float Ic = __ldg(pc);
                float Ix = 0.5f*(__ldg(pc+1)  - __ldg(pc-1));
                float Iy = 0.5f*(__ldg(pc+WW) - __ldg(pc-WW));
                float DI = Iw[c] - Ic;
                float u  = DI * (1.0f/LAM);
                float wt = rsqrtf(fmaf(u, u, 1.0f));
                float wd = wt * DI;
                float d[6] = {Ix, Iy, Ix*X, Ix*Y, Iy*X, Iy*Y};
                float t[6];
#pragma unroll
                for (int m = 0; m < 6; m++) t[m] = wt * d[m];
                int id = 0;
#pragma unroll
                for (int m = 0; m < 6; m++)
#pragma unroll
                    for (int n = m; n < 6; n++) { acc[id] = fmaf(t[m], d[n], acc[id]); id++; }
#pragma unroll
                for (int m = 0; m < 6; m++) acc[21+m] = fmaf(d[m], wd, acc[21+m]);
            }
        }
    }

    int tid = threadIdx.y*TBX + threadIdx.x;
    int lane = tid & 31, wid = tid >> 5;
#pragma unroll
    for (int k = 0; k < 27; k++) {
        float v = acc[k];
#pragma unroll
        for (int o = 16; o > 0; o >>= 1) v += __shfl_xor_sync(0xffffffffu, v, o);
        if (lane == 0) sred[wid][k] = v;
    }
    __syncthreads();
    if (tid < 27) {
        float s = 0.0f;
#pragma unroll
        for (int wq = 0; wq < NTHR/32; wq++) s += sred[wq][tid];
        g_part[(b*NBLK1 + blockIdx.x)*27 + tid] = s;
    }

    // last-arriving block performs the solve
    __syncthreads();
    __threadfence();
    if (tid == 0) {
        int prev = atomicAdd(&g_cnt[b], 1);
        s_last = (prev == NBLK1 - 1);
        if (s_last) g_cnt[b] = 0;
    }
    __syncthreads();
    if (!s_last) return;

    // ---- parallel tail sum: 8 threads per entry, deterministic order ----
    __shared__ double st[27][8];
    __shared__ double sS[27];
    if (tid < 216) {
        int val = tid >> 3, j = tid & 7;
        double a = 0.0;
        for (int k = j; k < NBLK1; k += 8)
            a += (double)g_part[(b*NBLK1 + k)*27 + val];
        st[val][j] = a;
    }
    __syncthreads();
    if (tid < 27) {
        double a = 0.0;
#pragma unroll
        for (int j = 0; j < 8; j++) a += st[tid][j];
        sS[tid] = a;
    }
    __syncthreads();
    if (tid != 0) return;

    {
        __shared__ double sA[6][7];
        int id = 0;
        for (int m = 0; m < 6; m++)
            for (int n = m; n < 6; n++) { sA[m][n] = sS[id]; sA[n][m] = sS[id]; id++; }
        for (int m = 0; m < 6; m++) { sA[m][m] += 1e-6; sA[m][6] = sS[21+m]; }

        for (int k = 0; k < 6; k++) {
            int piv = k; double best = fabs(sA[k][k]);
            for (int i = k+1; i < 6; i++) { double vv = fabs(sA[i][k]); if (vv > best) { best = vv; piv = i; } }
            if (piv != k)
                for (int j = 0; j < 7; j++) { double tmp = sA[k][j]; sA[k][j] = sA[piv][j]; sA[piv][j] = tmp; }
            double inv = 1.0 / sA[k][k];
            for (int i = k+1; i < 6; i++) {
                double f = sA[i][k] * inv;
                for (int j = k; j < 7; j++) sA[i][j] -= f * sA[k][j];
            }
        }
        float dp[6];
        double n2 = 0.0;
        for (int i = 5; i >= 0; i--) {
            double vv = sA[i][6];
            for (int j = i+1; j < 6; j++) vv -= sA[i][j] * (double)dp[j];
            double di = vv / sA[i][i];
            dp[i] = (float)di;
            n2 += di*di;
        }

        float* pw = &g_p[b*NPAR];
        float q0 = pw[0], q1 = pw[1], q2 = pw[2], q3 = pw[3], q4 = pw[4], q5 = pw[5];
        float a00 = 1.0f+q2, a01 = q3, a02 = q0, a10 = q4, a11 = 1.0f+q5, a12 = q1;
        float b00 = 1.0f+dp[2], b01 = dp[3], b02 = dp[0], b10 = dp[4], b11 = 1.0f+dp[5], b12 = dp[1];
        float det = b00*b11 - b01*b10;
        float rdet = 1.0f/det;
        float c00 =  b11*rdet, c01 = -b01*rdet, c10 = -b10*rdet, c11 =  b00*rdet;
        float c02 = -(c00*b02 + c01*b12);
        float c12 = -(c10*b02 + c11*b12);
        pw[0] = a00*c02 + a01*c12 + a02;
        pw[1] = a10*c02 + a11*c12 + a12;
        pw[2] = a00*c00 + a01*c10 - 1.0f;
        pw[3] = a00*c01 + a01*c11;
        pw[4] = a10*c00 + a11*c10;
        pw[5] = a10*c01 + a11*c11 - 1.0f;
        if (sqrt(n2) < (double)TOLF) g_done[b] = 1;
    }
}

// -------- final pass: Iw, DI outputs + robust error (fused finalize) --------
__global__ void __launch_bounds__(FBX*FBY) k_final(float* __restrict__ out) {
    int b = blockIdx.y;
    __shared__ float sr[(FBX*FBY)/32][2];
    __shared__ int s_last;
    const float* pb = &g_p[b*NPAR];
    float p0 = pb[0], p1 = pb[1], p2 = pb[2], p3 = pb[3], p4 = pb[4], p5 = pb[5];
    const float* I1b = g_I1p + b*CC*PIX;
    const float* I2b = g_I2p + b*CC*PIX;
    float* outDI = out + OUT_DI + (size_t)b*PIX*CC;
    float* outIW = out + OUT_IW + (size_t)b*PIX*CC;

    float rsum = 0.0f, csum = 0.0f;
    int rbase = blockIdx.x*ROWSF + threadIdx.y;
    for (int hr = 0; hr < ROWSF; hr += FBY) {
        int h = rbase + hr;
        float Y = (float)h;
        bool rowok = (h >= DELTA && h < HH-DELTA);
        for (int w = threadIdx.x; w < WW; w += FBX) {
            float X = (float)w;
            float xg = fmaf(1.0f + p2, X, fmaf(p3, Y, p0));
            float yg = fmaf(p4, X, fmaf(1.0f + p5, Y, p1));
            float Iw[3];
            bicubic3(I2b, xg, yg, Iw);
            float gx = rintf(xg), gy = rintf(yg);
            bool wm = (gx >= (float)DELTA && gx <= (float)(WW-DELTA) &&
                       gy >= (float)DELTA && gy <= (float)(HH-DELTA));
            bool m = wm && rowok && (w >= DELTA && w < WW-DELTA);
            int po = h*WW + w;
#pragma unroll
            for (int c = 0; c < CC; c++) {
                float di = m ? (Iw[c] - __ldg(I1b + c*PIX + po)) : 0.0f;
                outDI[po*3 + c] = di;
                outIW[po*3 + c] = Iw[c];
                if (m) {
                    float u = di * (1.0f/LAM);
                    rsum += (2.0f*LAM*LAM) * (sqrtf(fmaf(u, u, 1.0f)) - 1.0f);
                    csum += 1.0f;
                }
            }
        }
    }

    int tid = threadIdx.y*FBX + threadIdx.x;
    int lane = tid & 31, wid = tid >> 5;
#pragma unroll
    for (int o = 16; o > 0; o >>= 1) {
        rsum += __shfl_xor_sync(0xffffffffu, rsum, o);
        csum += __shfl_xor_sync(0xffffffffu, csum, o);
    }
    if (lane == 0) { sr[wid][0] = rsum; sr[wid][1] = csum; }
    __syncthreads();
    if (tid < 2) {
        float s = 0.0f;
#pragma unroll
        for (int wq = 0; wq < (FBX*FBY)/32; wq++) s += sr[wq][tid];
        g_fpart[(b*NBLKF + blockIdx.x)*2 + tid] = s;
    }

    __syncthreads();
    __threadfence();
    if (tid == 0) {
        int prev = atomicAdd(&g_fcnt[b], 1);
        s_last = (prev == NBLKF - 1);
        if (s_last) g_fcnt[b] = 0;
    }
    __syncthreads();
    if (!s_last) return;

    if (tid == 0) {
        double r = 0.0, c = 0.0;
        for (int k = 0; k < NBLKF; k++) {
            r += (double)g_fpart[(b*NBLKF + k)*2 + 0];
            c += (double)g_fpart[(b*NBLKF + k)*2 + 1];
        }
        double cnt = c < 1.0 ? 1.0 : c;
        out[OUT_ERR + b] = (float)(r / cnt);
    }
    if (tid < NPAR) out[OUT_P + b*NPAR + tid] = g_p[b*NPAR + tid];
}

// -------- entry --------
extern "C" void kernel_launch(void* const* d_in, const int* in_sizes, int n_in,
                              void* d_out, int out_size) {
    const float* I1  = (const float*)d_in[0];
    const float* I2  = (const float*)d_in[1];
    const float* pin = (const float*)d_in[2];
    float* out = (float*)d_out;

    k_init<<<(BB*PIX + 255)/256, 256>>>(I1, I2, pin);
    for (int it = 0; it < MAXIT; it++)
        k_iter<<<dim3(NBLK1, BB), dim3(TBX, TBY)>>>();
    k_final<<<dim3(NBLKF, BB), dim3(FBX, FBY)>>>(out);
}

// round 14
// speedup vs baseline: 1.3585x; 1.2832x over previous
#include <cuda_runtime.h>
#include <math.h>

#define BB 8
#define HH 384
#define WW 384
#define CC 3
#define NPAR 6
#define DELTA 10
#define LAM 0.05f
#define TOLF 1e-3f
#define MAXIT 12

#define PIX (HH*WW)
#define VH (HH - 2*DELTA)   // 364

#define TBX 128
#define TBY 2
#define NTHR (TBX*TBY)      // 256
#define ROWS1 4
#define NBLK1 (VH/ROWS1)    // 91

#define FBX 128
#define FBY 2
#define ROWSF 4
#define NBLKF (HH/ROWSF)    // 96

// Output layout: pf[B*6] | err[B] | DI[B*H*W*C] | Iw[B*H*W*C]
#define OUT_P   0
#define OUT_ERR (BB*NPAR)
#define OUT_DI  (BB*NPAR + BB)
#define OUT_IW  (OUT_DI + BB*PIX*CC)

// -------- scratch --------
__device__ float g_I1p[BB*CC*PIX];
__device__ float g_I2p[BB*CC*PIX];
__device__ float g_p[BB*NPAR];
__device__ int   g_done[BB];
__device__ float g_part[BB*NBLK1*27];
__device__ int   g_cnt[BB];
__device__ float g_fpart[BB*NBLKF*2];
__device__ int   g_fcnt[BB];

// -------- helpers --------
__device__ __forceinline__ float cubw(float s) {
    s = fabsf(s);
    float s2 = s*s, s3 = s2*s;
    float w1 = 1.5f*s3 - 2.5f*s2 + 1.0f;
    float w2 = -0.5f*s3 + 2.5f*s2 - 4.0f*s + 2.0f;
    return (s <= 1.0f) ? w1 : ((s < 2.0f) ? w2 : 0.0f);
}

__device__ __forceinline__ void bicubic3(const float* __restrict__ I2b,
                                         float xg, float yg, float out[3]) {
    float x0 = floorf(xg), y0 = floorf(yg);
    float tx = xg - x0, ty = yg - y0;
    int xi = (int)x0, yi = (int)y0;
    float wx[4], wy[4];
    int xx[4], yy[4];
#pragma unroll
    for (int k = 0; k < 4; k++) {
        wx[k] = cubw(tx - (float)(k - 1));
        wy[k] = cubw(ty - (float)(k - 1));
        int xc = xi + k - 1; xc = xc < 0 ? 0 : (xc > WW-1 ? WW-1 : xc);
        int yc = yi + k - 1; yc = yc < 0 ? 0 : (yc > HH-1 ? HH-1 : yc);
        xx[k] = xc; yy[k] = yc;
    }
#pragma unroll
    for (int c = 0; c < CC; c++) {
        const float* pc = I2b + c*PIX;
        float acc = 0.0f;
#pragma unroll
        for (int j = 0; j < 4; j++) {
            const float* pr = pc + yy[j]*WW;
            float r = wx[0]*__ldg(pr+xx[0]) + wx[1]*__ldg(pr+xx[1])
                    + wx[2]*__ldg(pr+xx[2]) + wx[3]*__ldg(pr+xx[3]);
            acc = fmaf(wy[j], r, acc);
        }
        out[c] = acc;
    }
}

// packed upper-tri diagonal indices for 6x6: (i,i) -> {0,6,11,15,18,20}
__device__ __constant__ int c_diag[6] = {0, 6, 11, 15, 18, 20};

// -------- init: planarize images, load p, reset state --------
__global__ void k_init(const float* __restrict__ I1,
                       const float* __restrict__ I2,
                       const float* __restrict__ pin) {
    int gid = blockIdx.x*blockDim.x + threadIdx.x;
    if (gid < BB*NPAR) g_p[gid] = pin[gid];
    if (gid < BB) { g_done[gid] = 0; g_cnt[gid] = 0; g_fcnt[gid] = 0; }
    if (gid < BB*PIX) {
        int b = gid / PIX;
        int r = gid - b*PIX;
#pragma unroll
        for (int c = 0; c < CC; c++) {
            int po = (b*CC + c)*PIX + r;
            g_I1p[po] = I1[gid*3 + c];
            g_I2p[po] = I2[gid*3 + c];
        }
    }
}

// -------- iteration: R5 27-accumulator body + fused FAST solve --------
__global__ void __launch_bounds__(NTHR, 3) k_iter() {
    int b = blockIdx.y;
    __shared__ float sred[NTHR/32][27];
    __shared__ int s_last;
    if (g_done[b]) return;
    const float* pb = &g_p[b*NPAR];
    float p0 = pb[0], p1 = pb[1], p2 = pb[2], p3 = pb[3], p4 = pb[4], p5 = pb[5];
    const float* I1b = g_I1p + b*CC*PIX;
    const float* I2b = g_I2p + b*CC*PIX;

    float acc[27];
#pragma unroll
    for (int k = 0; k < 27; k++) acc[k] = 0.0f;

    int rbase = DELTA + blockIdx.x*ROWS1 + threadIdx.y;
    for (int hr = 0; hr < ROWS1; hr += TBY) {
        int h = rbase + hr;
        float Y = (float)h;
        for (int w = DELTA + threadIdx.x; w < WW - DELTA; w += TBX) {
            float X = (float)w;
            float xg = fmaf(1.0f + p2, X, fmaf(p3, Y, p0));
            float yg = fmaf(p4, X, fmaf(1.0f + p5, Y, p1));
            float gx = rintf(xg), gy = rintf(yg);
            if (!(gx >= (float)DELTA && gx <= (float)(WW-DELTA) &&
                  gy >= (float)DELTA && gy <= (float)(HH-DELTA))) continue;

            float Iw[3];
            bicubic3(I2b, xg, yg, Iw);

#pragma unroll
            for (int c = 0; c < CC; c++) {
                const float* pc = I1b + c*PIX + h*WW + w;
                float Ic = __ldg(pc);
                float Ix = 0.5f*(__ldg(pc+1)  - __ldg(pc-1));
                float Iy = 0.5f*(__ldg(pc+WW) - __ldg(pc-WW));
                float DI = Iw[c] - Ic;
                float u  = DI * (1.0f/LAM);
                float wt = rsqrtf(fmaf(u, u, 1.0f));
                float wd = wt * DI;
                float d[6] = {Ix, Iy, Ix*X, Ix*Y, Iy*X, Iy*Y};
                float t[6];
#pragma unroll
                for (int m = 0; m < 6; m++) t[m] = wt * d[m];
                int id = 0;
#pragma unroll
                for (int m = 0; m < 6; m++)
#pragma unroll
                    for (int n = m; n < 6; n++) { acc[id] = fmaf(t[m], d[n], acc[id]); id++; }
#pragma unroll
                for (int m = 0; m < 6; m++) acc[21+m] = fmaf(d[m], wd, acc[21+m]);
            }
        }
    }

    int tid = threadIdx.y*TBX + threadIdx.x;
    int lane = tid & 31, wid = tid >> 5;
#pragma unroll
    for (int k = 0; k < 27; k++) {
        float v = acc[k];
#pragma unroll
        for (int o = 16; o > 0; o >>= 1) v += __shfl_xor_sync(0xffffffffu, v, o);
        if (lane == 0) sred[wid][k] = v;
    }
    __syncthreads();
    if (tid < 27) {
        float s = 0.0f;
#pragma unroll
        for (int wq = 0; wq < NTHR/32; wq++) s += sred[wq][tid];
        g_part[(b*NBLK1 + blockIdx.x)*27 + tid] = s;
    }

    // last-arriving block performs the solve
    __syncthreads();
    __threadfence();
    if (tid == 0) {
        int prev = atomicAdd(&g_cnt[b], 1);
        s_last = (prev == NBLK1 - 1);
        if (s_last) g_cnt[b] = 0;
    }
    __syncthreads();
    if (!s_last) return;

    // ---- parallel tail sum: 8 threads per entry, deterministic order ----
    __shared__ double st[27][8];
    __shared__ double sS[27];
    if (tid < 216) {
        int val = tid >> 3, j = tid & 7;
        double a = 0.0;
        for (int k = j; k < NBLK1; k += 8)
            a += (double)g_part[(b*NBLK1 + k)*27 + val];
        st[val][j] = a;
    }
    __syncthreads();
    if (tid < 27) {
        double a = 0.0;
#pragma unroll
        for (int j = 0; j < 8; j++) a += st[tid][j];
        sS[tid] = a;
    }
    __syncthreads();
    if (tid != 0) return;

    // ---- fast fp32 solve: Jacobi scaling (unit diagonal) + pivot-free
    //      Gaussian elimination. H is SPD + ridge -> stable without pivots;
    //      scaling kills the X,Y~374 grading (cond ~1e6 -> ~1e2).
    {
        __shared__ float fA[6][7];
        float sc[6];
#pragma unroll
        for (int i = 0; i < 6; i++)
            sc[i] = rsqrtf((float)(sS[c_diag[i]] + 1e-6));
        int id = 0;
#pragma unroll
        for (int m = 0; m < 6; m++)
#pragma unroll
            for (int n = m; n < 6; n++) {
                float v = (m == n) ? 1.0f
                        : (float)sS[id] * sc[m] * sc[n];
                fA[m][n] = v; fA[n][m] = v; id++;
            }
#pragma unroll
        for (int i = 0; i < 6; i++) fA[i][6] = (float)sS[21+i] * sc[i];

#pragma unroll
        for (int k = 0; k < 6; k++) {
            float inv = 1.0f / fA[k][k];
#pragma unroll
            for (int i = k+1; i < 6; i++) {
                float f = fA[i][k] * inv;
#pragma unroll
                for (int j = k; j < 7; j++) fA[i][j] -= f * fA[k][j];
            }
        }
        float dp[6];
        float n2 = 0.0f;
#pragma unroll
        for (int i = 5; i >= 0; i--) {
            float v = fA[i][6];
#pragma unroll
            for (int j = i+1; j < 6; j++) v -= fA[i][j] * dp[j];
            dp[i] = v / fA[i][i];
        }
#pragma unroll
        for (int i = 0; i < 6; i++) { dp[i] *= sc[i]; n2 = fmaf(dp[i], dp[i], n2); }

        float* pw = &g_p[b*NPAR];
        float q0 = pw[0], q1 = pw[1], q2 = pw[2], q3 = pw[3], q4 = pw[4], q5 = pw[5];
        float a00 = 1.0f+q2, a01 = q3, a02 = q0, a10 = q4, a11 = 1.0f+q5, a12 = q1;
        float b00 = 1.0f+dp[2], b01 = dp[3], b02 = dp[0], b10 = dp[4], b11 = 1.0f+dp[5], b12 = dp[1];
        float det = b00*b11 - b01*b10;
        float rdet = 1.0f/det;
        float c00 =  b11*rdet, c01 = -b01*rdet, c10 = -b10*rdet, c11 =  b00*rdet;
        float c02 = -(c00*b02 + c01*b12);
        float c12 = -(c10*b02 + c11*b12);
        pw[0] = a00*c02 + a01*c12 + a02;
        pw[1] = a10*c02 + a11*c12 + a12;
        pw[2] = a00*c00 + a01*c10 - 1.0f;
        pw[3] = a00*c01 + a01*c11;
        pw[4] = a10*c00 + a11*c10;
        pw[5] = a10*c01 + a11*c11 - 1.0f;
        if (sqrtf(n2) < TOLF) g_done[b] = 1;
    }
}

// -------- final pass: Iw, DI outputs + robust error (fused finalize) --------
__global__ void __launch_bounds__(FBX*FBY) k_final(float* __restrict__ out) {
    int b = blockIdx.y;
    __shared__ float sr[(FBX*FBY)/32][2];
    __shared__ int s_last;
    const float* pb = &g_p[b*NPAR];
    float p0 = pb[0], p1 = pb[1], p2 = pb[2], p3 = pb[3], p4 = pb[4], p5 = pb[5];
    const float* I1b = g_I1p + b*CC*PIX;
    const float* I2b = g_I2p + b*CC*PIX;
    float* outDI = out + OUT_DI + (size_t)b*PIX*CC;
    float* outIW = out + OUT_IW + (size_t)b*PIX*CC;

    float rsum = 0.0f, csum = 0.0f;
    int rbase = blockIdx.x*ROWSF + threadIdx.y;
    for (int hr = 0; hr < ROWSF; hr += FBY) {
        int h = rbase + hr;
        float Y = (float)h;
        bool rowok = (h >= DELTA && h < HH-DELTA);
        for (int w = threadIdx.x; w < WW; w += FBX) {
            float X = (float)w;
            float xg = fmaf(1.0f + p2, X, fmaf(p3, Y, p0));
            float yg = fmaf(p4, X, fmaf(1.0f + p5, Y, p1));
            float Iw[3];
            bicubic3(I2b, xg, yg, Iw);
            float gx = rintf(xg), gy = rintf(yg);
            bool wm = (gx >= (float)DELTA && gx <= (float)(WW-DELTA) &&
                       gy >= (float)DELTA && gy <= (float)(HH-DELTA));
            bool m = wm && rowok && (w >= DELTA && w < WW-DELTA);
            int po = h*WW + w;
#pragma unroll
            for (int c = 0; c < CC; c++) {
                float di = m ? (Iw[c] - __ldg(I1b + c*PIX + po)) : 0.0f;
                outDI[po*3 + c] = di;
                outIW[po*3 + c] = Iw[c];
                if (m) {
                    float u = di * (1.0f/LAM);
                    rsum += (2.0f*LAM*LAM) * (sqrtf(fmaf(u, u, 1.0f)) - 1.0f);
                    csum += 1.0f;
                }
            }
        }
    }

    int tid = threadIdx.y*FBX + threadIdx.x;
    int lane = tid & 31, wid = tid >> 5;
#pragma unroll
    for (int o = 16; o > 0; o >>= 1) {
        rsum += __shfl_xor_sync(0xffffffffu, rsum, o);
        csum += __shfl_xor_sync(0xffffffffu, csum, o);
    }
    if (lane == 0) { sr[wid][0] = rsum; sr[wid][1] = csum; }
    __syncthreads();
    if (tid < 2) {
        float s = 0.0f;
#pragma unroll
        for (int wq = 0; wq < (FBX*FBY)/32; wq++) s += sr[wq][tid];
        g_fpart[(b*NBLKF + blockIdx.x)*2 + tid] = s;
    }

    __syncthreads();
    __threadfence();
    if (tid == 0) {
        int prev = atomicAdd(&g_fcnt[b], 1);
        s_last = (prev == NBLKF - 1);
        if (s_last) g_fcnt[b] = 0;
    }
    __syncthreads();
    if (!s_last) return;

    if (tid == 0) {
        double r = 0.0, c = 0.0;
        for (int k = 0; k < NBLKF; k++) {
            r += (double)g_fpart[(b*NBLKF + k)*2 + 0];
            c += (double)g_fpart[(b*NBLKF + k)*2 + 1];
        }
        double cnt = c < 1.0 ? 1.0 : c;
        out[OUT_ERR + b] = (float)(r / cnt);
    }
    if (tid < NPAR) out[OUT_P + b*NPAR + tid] = g_p[b*NPAR + tid];
}

// -------- entry --------
extern "C" void kernel_launch(void* const* d_in, const int* in_sizes, int n_in,
                              void* d_out, int out_size) {
    const float* I1  = (const float*)d_in[0];
    const float* I2  = (const float*)d_in[1];
    const float* pin = (const float*)d_in[2];
    float* out = (float*)d_out;

    k_init<<<(BB*PIX + 255)/256, 256>>>(I1, I2, pin);
    for (int it = 0; it < MAXIT; it++)
        k_iter<<<dim3(NBLK1, BB), dim3(TBX, TBY)>>>();
    k_final<<<dim3(NBLKF, BB), dim3(FBX, FBY)>>>(out);
}